// round 4
// baseline (speedup 1.0000x reference)
#include <cuda_runtime.h>
#include <cuda_bf16.h>
#include <cstdint>

// Problem: y = x * softplus(x@W1^T + b1) * sum_n((x@W2^T+b2)*(x@W3^T+b3))
// B=4, L=2048 -> T=8192 tokens, D=1024, N=16. A is dead math.

#define T_TOKENS 8192
#define DMODEL   1024
#define NSTATE   16

__device__ float g_bc[T_TOKENS];  // per-token scalar sum_n(B*C)

// ---------------------------------------------------------------------------
// Kernel 1: bc[t] = sum_n (x[t]·W2[n] + b2[n]) * (x[t]·W3[n] + b3[n])
// 64 tokens per block, 256 threads: thread = (gid 0..15, n 0..15), 4 tokens each.
// ---------------------------------------------------------------------------
__global__ __launch_bounds__(256) void bc_kernel(
    const float* __restrict__ x,
    const float* __restrict__ W2, const float* __restrict__ b2,
    const float* __restrict__ W3, const float* __restrict__ b3)
{
    const int TPB = 64;   // tokens per block
    const int KC  = 32;   // k chunk

    __shared__ float xs[TPB][36];    // [token][k] padded
    __shared__ float w2s[NSTATE][36];
    __shared__ float w3s[NSTATE][36];
    __shared__ float red[TPB][17];

    int tid = threadIdx.x;
    int n   = tid & 15;        // state index
    int gid = tid >> 4;        // token group 0..15
    int rowBase = blockIdx.x * TPB;

    float accB[4] = {0.f, 0.f, 0.f, 0.f};
    float accC[4] = {0.f, 0.f, 0.f, 0.f};

    for (int k0 = 0; k0 < DMODEL; k0 += KC) {
        // load x chunk: 64 x 32 floats = 512 float4, 2 per thread
        #pragma unroll
        for (int j = 0; j < 2; j++) {
            int f = tid * 2 + j;           // 0..511
            int row = f >> 3;              // 8 float4 per row
            int q   = f & 7;
            float4 v = *reinterpret_cast<const float4*>(
                x + (size_t)(rowBase + row) * DMODEL + k0 + q * 4);
            xs[row][q*4+0] = v.x; xs[row][q*4+1] = v.y;
            xs[row][q*4+2] = v.z; xs[row][q*4+3] = v.w;
        }
        // load W2/W3 chunk: 16 x 32 each = 128 float4 each
        {
            int f = tid & 127;
            int row = f >> 3;
            int q   = f & 7;
            const float* src = (tid < 128) ? W2 : W3;
            float4 v = *reinterpret_cast<const float4*>(
                src + (size_t)row * DMODEL + k0 + q * 4);
            float (*dst)[36] = (tid < 128) ? w2s : w3s;
            dst[row][q*4+0] = v.x; dst[row][q*4+1] = v.y;
            dst[row][q*4+2] = v.z; dst[row][q*4+3] = v.w;
        }
        __syncthreads();

        #pragma unroll 8
        for (int kk = 0; kk < KC; kk++) {
            float w2 = w2s[n][kk];
            float w3 = w3s[n][kk];
            #pragma unroll
            for (int t = 0; t < 4; t++) {
                float xv = xs[gid*4 + t][kk];
                accB[t] = fmaf(xv, w2, accB[t]);
                accC[t] = fmaf(xv, w3, accC[t]);
            }
        }
        __syncthreads();
    }

    float bb = b2[n], bb3 = b3[n];
    #pragma unroll
    for (int t = 0; t < 4; t++)
        red[gid*4 + t][n] = (accB[t] + bb) * (accC[t] + bb3);
    __syncthreads();

    if (tid < TPB) {
        float s = 0.f;
        #pragma unroll
        for (int nn = 0; nn < NSTATE; nn++) s += red[tid][nn];
        g_bc[rowBase + tid] = s;
    }
}

// ---------------------------------------------------------------------------
// Packed f32x2 helpers (sm_103a FFMA2 — only reachable via PTX)
// ---------------------------------------------------------------------------
__device__ __forceinline__ unsigned long long pack_dup(float v) {
    unsigned long long r;
    unsigned int u = __float_as_uint(v);
    asm("mov.b64 %0, {%1, %1};" : "=l"(r) : "r"(u));
    return r;
}
__device__ __forceinline__ void ffma2(unsigned long long& d,
                                      unsigned long long a,
                                      unsigned long long b) {
    asm("fma.rn.f32x2 %0, %1, %2, %0;" : "+l"(d) : "l"(a), "l"(b));
}
__device__ __forceinline__ float2 unpack2(unsigned long long v) {
    float2 r;
    unsigned int lo, hi;
    asm("mov.b64 {%0, %1}, %2;" : "=r"(lo), "=r"(hi) : "l"(v));
    r.x = __uint_as_float(lo); r.y = __uint_as_float(hi);
    return r;
}

__device__ __forceinline__ float softplus_f(float z) {
    // log1p(exp(z)) computed stably: max(z,0) + log1p(exp(-|z|))
    return fmaxf(z, 0.f) + log1pf(expf(-fabsf(z)));
}

// ---------------------------------------------------------------------------
// Kernel 2: tiled fp32 GEMM y = x @ W1^T with fused epilogue
//   y[t,j] = x[t,j] * softplus(acc + b1[j]) * bc[t]
// Tiles: 128x128x16, 256 threads, 8x8 micro-tile per thread, FFMA2 inner.
// Register-prefetch pipeline: next tile's LDG.128s issue before computing
// the current tile, overlapping ~250cyc L2 latency with the FFMA2 burst.
// ---------------------------------------------------------------------------
#define BM 128
#define BN 128
#define BK 16

__global__ __launch_bounds__(256) void gemm_fused_kernel(
    const float* __restrict__ x,
    const float* __restrict__ W1,
    const float* __restrict__ b1,
    float* __restrict__ y)
{
    __shared__ float As[BK][BM];   // [k][m]  x tile (transposed)
    __shared__ float Bs[BK][BN];   // [k][n]  W1 tile (transposed)

    int tid = threadIdx.x;
    int tx  = tid & 15;            // col group (8 cols each)
    int ty  = tid >> 4;            // row group (8 rows each)
    int rowBase = blockIdx.y * BM;
    int colBase = blockIdx.x * BN;

    // 32 packed accumulators: [row i][col pair jp] covering cols 2jp, 2jp+1
    unsigned long long acc[8][4];
    #pragma unroll
    for (int i = 0; i < 8; i++)
        #pragma unroll
        for (int j = 0; j < 4; j++) acc[i][j] = 0ull;

    const float* xBase  = x  + (size_t)rowBase * DMODEL;
    const float* wBase  = W1 + (size_t)colBase * DMODEL;

    // Per-thread load coords: f = tid*2 + j, row = f>>2 (4 float4 per 16-wide
    // row), q = f&3. Both j's hit the same row, consecutive q.
    const int ldRow = (tid * 2) >> 2;
    const int ldQ0  = (tid * 2) & 3;       // j=0 -> q, j=1 -> q+1

    float4 pa[2], pb[2];

    // prefetch tile 0
    #pragma unroll
    for (int j = 0; j < 2; j++) {
        pa[j] = *reinterpret_cast<const float4*>(
            xBase + (size_t)ldRow * DMODEL + (ldQ0 + j) * 4);
        pb[j] = *reinterpret_cast<const float4*>(
            wBase + (size_t)ldRow * DMODEL + (ldQ0 + j) * 4);
    }

    for (int k0 = 0; k0 < DMODEL; k0 += BK) {
        // store prefetched regs to smem
        #pragma unroll
        for (int j = 0; j < 2; j++) {
            int q = ldQ0 + j;
            As[q*4+0][ldRow] = pa[j].x; As[q*4+1][ldRow] = pa[j].y;
            As[q*4+2][ldRow] = pa[j].z; As[q*4+3][ldRow] = pa[j].w;
            Bs[q*4+0][ldRow] = pb[j].x; Bs[q*4+1][ldRow] = pb[j].y;
            Bs[q*4+2][ldRow] = pb[j].z; Bs[q*4+3][ldRow] = pb[j].w;
        }
        __syncthreads();

        // prefetch next tile (overlaps with compute below)
        if (k0 + BK < DMODEL) {
            #pragma unroll
            for (int j = 0; j < 2; j++) {
                pa[j] = *reinterpret_cast<const float4*>(
                    xBase + (size_t)ldRow * DMODEL + (k0 + BK) + (ldQ0 + j) * 4);
                pb[j] = *reinterpret_cast<const float4*>(
                    wBase + (size_t)ldRow * DMODEL + (k0 + BK) + (ldQ0 + j) * 4);
            }
        }

        #pragma unroll
        for (int kk = 0; kk < BK; kk++) {
            // A fragment: 8 row values, duplicated into f32x2
            const float4* Ap = reinterpret_cast<const float4*>(&As[kk][ty*8]);
            float4 a0 = Ap[0], a1 = Ap[1];
            unsigned long long ap[8];
            ap[0] = pack_dup(a0.x); ap[1] = pack_dup(a0.y);
            ap[2] = pack_dup(a0.z); ap[3] = pack_dup(a0.w);
            ap[4] = pack_dup(a1.x); ap[5] = pack_dup(a1.y);
            ap[6] = pack_dup(a1.z); ap[7] = pack_dup(a1.w);
            // B fragment: 8 col values = 4 natural f32x2 pairs
            const ulonglong2* Bp = reinterpret_cast<const ulonglong2*>(&Bs[kk][tx*8]);
            ulonglong2 b01 = Bp[0], b23 = Bp[1];
            unsigned long long bp[4] = {b01.x, b01.y, b23.x, b23.y};
            #pragma unroll
            for (int i = 0; i < 8; i++) {
                ffma2(acc[i][0], ap[i], bp[0]);
                ffma2(acc[i][1], ap[i], bp[1]);
                ffma2(acc[i][2], ap[i], bp[2]);
                ffma2(acc[i][3], ap[i], bp[3]);
            }
        }
        __syncthreads();
    }

    // Epilogue: y[t,j] = x[t,j] * softplus(acc + b1[j]) * bc[t]
    #pragma unroll
    for (int i = 0; i < 8; i++) {
        int row = rowBase + ty*8 + i;
        float bcv = g_bc[row];
        const float* xrow = x + (size_t)row * DMODEL;
        float* yrow = y + (size_t)row * DMODEL;
        #pragma unroll
        for (int jp = 0; jp < 4; jp++) {
            int col = colBase + tx*8 + jp*2;
            float2 z = unpack2(acc[i][jp]);
            float d0 = softplus_f(z.x + b1[col]);
            float d1 = softplus_f(z.y + b1[col+1]);
            yrow[col]   = xrow[col]   * d0 * bcv;
            yrow[col+1] = xrow[col+1] * d1 * bcv;
        }
    }
}

// ---------------------------------------------------------------------------
extern "C" void kernel_launch(void* const* d_in, const int* in_sizes, int n_in,
                              void* d_out, int out_size)
{
    const float* x  = (const float*)d_in[0];
    const float* W1 = (const float*)d_in[1];
    const float* b1 = (const float*)d_in[2];
    const float* W2 = (const float*)d_in[3];
    const float* b2 = (const float*)d_in[4];
    const float* W3 = (const float*)d_in[5];
    const float* b3 = (const float*)d_in[6];
    // d_in[7] = A : dead math (multiplied by zero state), unused.
    float* y = (float*)d_out;

    bc_kernel<<<T_TOKENS / 64, 256>>>(x, W2, b2, W3, b3);
    gemm_fused_kernel<<<dim3(DMODEL / BN, T_TOKENS / BM), 256>>>(x, W1, b1, y);
}

// round 7
// speedup vs baseline: 1.9819x; 1.9819x over previous
#include <cuda_runtime.h>
#include <cuda_bf16.h>
#include <cstdint>

// y = x * softplus(x@W1^T + b1) * sum_n((x@W2^T+b2)*(x@W3^T+b3))
// B=4, L=2048 -> T=8192 tokens, D=1024, N=16. A input is dead math.
//
// Round 6: tcgen05 is NOT reachable (harness PTX target = sm_103 base, no 'a').
// Tensor path via legacy mma.sync.m16n8k16.bf16 (HMMA) + ldmatrix + cp.async.
// 3-pass split precision: x=xh+xl, W1=wh+wl (bf16):
//   z = xh@wh^T + xl@wh^T + xh@wl^T   (xl@wl dropped, ~2^-18 rel)

#define T_TOKENS 8192
#define DMODEL   1024
#define NSTATE   16

__device__ float          g_bc[T_TOKENS];
__device__ __nv_bfloat16  g_xh[T_TOKENS * DMODEL];
__device__ __nv_bfloat16  g_xl[T_TOKENS * DMODEL];
__device__ __nv_bfloat16  g_wh[DMODEL * DMODEL];
__device__ __nv_bfloat16  g_wl[DMODEL * DMODEL];

// ---------------------------------------------------------------------------
__device__ __forceinline__ uint32_t smem_u32(const void* p) {
    uint32_t a;
    asm("{ .reg .u64 t; cvta.to.shared.u64 t, %1; cvt.u32.u64 %0, t; }"
        : "=r"(a) : "l"(p));
    return a;
}

#define SW128(o) ((o) ^ (((o) >> 3) & 0x70))

#define CP_ASYNC16(dst, src) \
    asm volatile("cp.async.cg.shared.global [%0], [%1], 16;" \
                 :: "r"(dst), "l"(src) : "memory")
#define CP_COMMIT() asm volatile("cp.async.commit_group;" ::: "memory")
#define CP_WAIT1()  asm volatile("cp.async.wait_group 1;" ::: "memory")
#define CP_WAIT0()  asm volatile("cp.async.wait_group 0;" ::: "memory")

#define LDSM4(r, addr) \
    asm volatile("ldmatrix.sync.aligned.m8n8.x4.shared.b16 {%0,%1,%2,%3}, [%4];" \
        : "=r"((r)[0]), "=r"((r)[1]), "=r"((r)[2]), "=r"((r)[3]) : "r"(addr))

#define MMA16816(d, a, b0v, b1v) \
    asm volatile("mma.sync.aligned.m16n8k16.row.col.f32.bf16.bf16.f32 " \
        "{%0,%1,%2,%3}, {%4,%5,%6,%7}, {%8,%9}, {%0,%1,%2,%3};" \
        : "+f"((d)[0]), "+f"((d)[1]), "+f"((d)[2]), "+f"((d)[3]) \
        : "r"((a)[0]), "r"((a)[1]), "r"((a)[2]), "r"((a)[3]), \
          "r"(b0v), "r"(b1v))

__device__ __forceinline__ float softplus_f(float z) {
    return fmaxf(z, 0.f) + log1pf(expf(-fabsf(z)));
}

// ---------------------------------------------------------------------------
// Kernel A: fp32 -> (bf16 hi, bf16 lo) split. One float4 per thread.
// ---------------------------------------------------------------------------
__global__ __launch_bounds__(256) void split_kernel(
    const float* __restrict__ src, __nv_bfloat16* __restrict__ hi,
    __nv_bfloat16* __restrict__ lo, int n4)
{
    int i = blockIdx.x * blockDim.x + threadIdx.x;
    if (i >= n4) return;
    float4 v = reinterpret_cast<const float4*>(src)[i];
    float f[4] = {v.x, v.y, v.z, v.w};
    __nv_bfloat16 h[4], l[4];
    #pragma unroll
    for (int j = 0; j < 4; j++) {
        h[j] = __float2bfloat16(f[j]);
        l[j] = __float2bfloat16(f[j] - __bfloat162float(h[j]));
    }
    ushort4 ho, lov;
    ho.x = *(unsigned short*)&h[0]; ho.y = *(unsigned short*)&h[1];
    ho.z = *(unsigned short*)&h[2]; ho.w = *(unsigned short*)&h[3];
    lov.x = *(unsigned short*)&l[0]; lov.y = *(unsigned short*)&l[1];
    lov.z = *(unsigned short*)&l[2]; lov.w = *(unsigned short*)&l[3];
    reinterpret_cast<ushort4*>(hi)[i] = ho;
    reinterpret_cast<ushort4*>(lo)[i] = lov;
}

// ---------------------------------------------------------------------------
// Kernel B: bc[t] = sum_n (x[t]·W2[n] + b2[n]) * (x[t]·W3[n] + b3[n])
// ---------------------------------------------------------------------------
__global__ __launch_bounds__(256) void bc_kernel(
    const float* __restrict__ x,
    const float* __restrict__ W2, const float* __restrict__ b2,
    const float* __restrict__ W3, const float* __restrict__ b3)
{
    const int TPB = 64, KC = 32;
    __shared__ float xs[TPB][36];
    __shared__ float w2s[NSTATE][36];
    __shared__ float w3s[NSTATE][36];
    __shared__ float red[TPB][17];

    int tid = threadIdx.x;
    int n   = tid & 15;
    int gid = tid >> 4;
    int rowBase = blockIdx.x * TPB;

    float accB[4] = {0.f, 0.f, 0.f, 0.f};
    float accC[4] = {0.f, 0.f, 0.f, 0.f};

    for (int k0 = 0; k0 < DMODEL; k0 += KC) {
        #pragma unroll
        for (int j = 0; j < 2; j++) {
            int f = tid * 2 + j, row = f >> 3, q = f & 7;
            float4 v = *reinterpret_cast<const float4*>(
                x + (size_t)(rowBase + row) * DMODEL + k0 + q * 4);
            xs[row][q*4+0] = v.x; xs[row][q*4+1] = v.y;
            xs[row][q*4+2] = v.z; xs[row][q*4+3] = v.w;
        }
        {
            int f = tid & 127, row = f >> 3, q = f & 7;
            const float* src = (tid < 128) ? W2 : W3;
            float4 v = *reinterpret_cast<const float4*>(
                src + (size_t)row * DMODEL + k0 + q * 4);
            float (*dst)[36] = (tid < 128) ? w2s : w3s;
            dst[row][q*4+0] = v.x; dst[row][q*4+1] = v.y;
            dst[row][q*4+2] = v.z; dst[row][q*4+3] = v.w;
        }
        __syncthreads();

        #pragma unroll 8
        for (int kk = 0; kk < KC; kk++) {
            float w2 = w2s[n][kk], w3 = w3s[n][kk];
            #pragma unroll
            for (int t = 0; t < 4; t++) {
                float xv = xs[gid*4 + t][kk];
                accB[t] = fmaf(xv, w2, accB[t]);
                accC[t] = fmaf(xv, w3, accC[t]);
            }
        }
        __syncthreads();
    }

    float bb = b2[n], bb3 = b3[n];
    #pragma unroll
    for (int t = 0; t < 4; t++)
        red[gid*4 + t][n] = (accB[t] + bb) * (accC[t] + bb3);
    __syncthreads();

    if (tid < TPB) {
        float s = 0.f;
        #pragma unroll
        for (int nn = 0; nn < NSTATE; nn++) s += red[tid][nn];
        g_bc[rowBase + tid] = s;
    }
}

// ---------------------------------------------------------------------------
// Kernel C: mma.sync bf16 GEMM + fused epilogue.
// CTA 128(M) x 128(N), 8 warps -> warp tile 64x32 (wm = wid&1, wn = wid>>2..).
// K chunks of 64 bf16 (128B SW128 rows), 48 chunks (3 passes x 16).
// cp.async double-buffered smem; ldmatrix fragments; 16 HMMA per warp-kstep.
// ---------------------------------------------------------------------------
#define NCHUNKS 48
#define TILE_B  16384                 // 128 rows x 128B
#define SMEM_TOTAL (4 * TILE_B)       // A0 B0 A1 B1 = 64 KB

__global__ __launch_bounds__(256) void mma_kernel(
    const float* __restrict__ x,
    const float* __restrict__ b1,
    float* __restrict__ y)
{
    extern __shared__ char smem[];
    const uint32_t sbase = smem_u32(smem);
    const int tid  = threadIdx.x;
    const int wid  = tid >> 5;
    const int lane = tid & 31;

    const int rowBase = blockIdx.y * 128;
    const int colBase = blockIdx.x * 128;

    const int wm = wid & 1;           // M half (64 rows)
    const int wn = wid >> 1;          // N quarter (32 cols)

    // pass pointers
    const __nv_bfloat16* Ap[3] = {
        g_xh + (size_t)rowBase * DMODEL,
        g_xl + (size_t)rowBase * DMODEL,
        g_xh + (size_t)rowBase * DMODEL };
    const __nv_bfloat16* Bp[3] = {
        g_wh + (size_t)colBase * DMODEL,
        g_wh + (size_t)colBase * DMODEL,
        g_wl + (size_t)colBase * DMODEL };

    const uint32_t abuf[2] = {sbase,              sbase + 2*TILE_B};
    const uint32_t bbuf[2] = {sbase + TILE_B,     sbase + 3*TILE_B};

    // per-thread cp.async coords: f = tid + u*256, row = f>>3, q = f&7 (16B)
    // per-lane ldmatrix coords
    const int a_row  = (lane & 7) + ((lane >> 3) & 1) * 8;       // 0..15
    const int a_byte = (lane >> 4) * 16;                          // k-half
    const int axor   = (a_row & 7) << 4;
    const int b_row  = ((lane >> 4) & 1) * 8 + (lane & 7);        // n within 16
    const int b_byte = ((lane >> 3) & 1) * 16;                    // k-half
    const int bxor   = (b_row & 7) << 4;

    float acc[4][4][4];
    #pragma unroll
    for (int mi = 0; mi < 4; mi++)
        #pragma unroll
        for (int ni = 0; ni < 4; ni++)
            #pragma unroll
            for (int r = 0; r < 4; r++) acc[mi][ni][r] = 0.f;

    // issue chunk 0
    {
        const __nv_bfloat16* pa = Ap[0];
        const __nv_bfloat16* pb = Bp[0];
        #pragma unroll
        for (int u = 0; u < 4; u++) {
            int f = tid + u * 256, row = f >> 3, q = f & 7;
            uint32_t off = SW128(row * 128 + q * 16);
            CP_ASYNC16(abuf[0] + off, pa + (size_t)row * DMODEL + q * 8);
            CP_ASYNC16(bbuf[0] + off, pb + (size_t)row * DMODEL + q * 8);
        }
        CP_COMMIT();
    }

    #pragma unroll 1
    for (int g = 0; g < NCHUNKS; g++) {
        const int buf = g & 1;
        if (g + 1 < NCHUNKS) {
            int gg = g + 1;
            const __nv_bfloat16* pa = Ap[gg >> 4];
            const __nv_bfloat16* pb = Bp[gg >> 4];
            int kc = (gg & 15) << 6;
            #pragma unroll
            for (int u = 0; u < 4; u++) {
                int f = tid + u * 256, row = f >> 3, q = f & 7;
                uint32_t off = SW128(row * 128 + q * 16);
                CP_ASYNC16(abuf[buf ^ 1] + off, pa + (size_t)row * DMODEL + kc + q * 8);
                CP_ASYNC16(bbuf[buf ^ 1] + off, pb + (size_t)row * DMODEL + kc + q * 8);
            }
            CP_COMMIT();
            CP_WAIT1();
        } else {
            CP_WAIT0();
        }
        __syncthreads();

        const uint32_t aB = abuf[buf];
        const uint32_t bB = bbuf[buf];

        #pragma unroll
        for (int s = 0; s < 4; s++) {
            const int kb = s * 32;                 // 16 bf16 = 32B per step
            uint32_t afr[4][4];
            #pragma unroll
            for (int mi = 0; mi < 4; mi++) {
                uint32_t addr = aB + (uint32_t)((wm * 64 + mi * 16 + a_row) * 128)
                              + (uint32_t)((kb + a_byte) ^ axor);
                LDSM4(afr[mi], addr);
            }
            uint32_t bfr[2][4];
            #pragma unroll
            for (int bt = 0; bt < 2; bt++) {
                uint32_t addr = bB + (uint32_t)((wn * 32 + bt * 16 + b_row) * 128)
                              + (uint32_t)((kb + b_byte) ^ bxor);
                LDSM4(bfr[bt], addr);
            }
            #pragma unroll
            for (int mi = 0; mi < 4; mi++) {
                #pragma unroll
                for (int ni = 0; ni < 4; ni++) {
                    const uint32_t* bq = bfr[ni >> 1];
                    int o = (ni & 1) * 2;
                    MMA16816(acc[mi][ni], afr[mi], bq[o], bq[o + 1]);
                }
            }
        }
        __syncthreads();
    }

    // Epilogue: y = x * softplus(z + b1) * bc
    const int gq = lane >> 2;    // row in tile
    const int tq = lane & 3;     // col pair
    #pragma unroll
    for (int mi = 0; mi < 4; mi++) {
        int r0 = rowBase + wm * 64 + mi * 16 + gq;
        int r1 = r0 + 8;
        float bc0 = g_bc[r0], bc1 = g_bc[r1];
        const float* x0 = x + (size_t)r0 * DMODEL;
        const float* x1 = x + (size_t)r1 * DMODEL;
        float* y0 = y + (size_t)r0 * DMODEL;
        float* y1 = y + (size_t)r1 * DMODEL;
        #pragma unroll
        for (int ni = 0; ni < 4; ni++) {
            int c = colBase + wn * 32 + ni * 8 + tq * 2;
            float2 bv  = *reinterpret_cast<const float2*>(b1 + c);
            float2 xv0 = *reinterpret_cast<const float2*>(x0 + c);
            float2 xv1 = *reinterpret_cast<const float2*>(x1 + c);
            float2 o0, o1;
            o0.x = xv0.x * softplus_f(acc[mi][ni][0] + bv.x) * bc0;
            o0.y = xv0.y * softplus_f(acc[mi][ni][1] + bv.y) * bc0;
            o1.x = xv1.x * softplus_f(acc[mi][ni][2] + bv.x) * bc1;
            o1.y = xv1.y * softplus_f(acc[mi][ni][3] + bv.y) * bc1;
            *reinterpret_cast<float2*>(y0 + c) = o0;
            *reinterpret_cast<float2*>(y1 + c) = o1;
        }
    }
}

// ---------------------------------------------------------------------------
extern "C" void kernel_launch(void* const* d_in, const int* in_sizes, int n_in,
                              void* d_out, int out_size)
{
    const float* x  = (const float*)d_in[0];
    const float* W1 = (const float*)d_in[1];
    const float* b1 = (const float*)d_in[2];
    const float* W2 = (const float*)d_in[3];
    const float* b2 = (const float*)d_in[4];
    const float* W3 = (const float*)d_in[5];
    const float* b3 = (const float*)d_in[6];
    float* y = (float*)d_out;

    __nv_bfloat16 *xh, *xl, *wh, *wl;
    cudaGetSymbolAddress((void**)&xh, g_xh);
    cudaGetSymbolAddress((void**)&xl, g_xl);
    cudaGetSymbolAddress((void**)&wh, g_wh);
    cudaGetSymbolAddress((void**)&wl, g_wl);

    int nx4 = T_TOKENS * DMODEL / 4;
    int nw4 = DMODEL * DMODEL / 4;
    split_kernel<<<nx4 / 256, 256>>>(x, xh, xl, nx4);
    split_kernel<<<nw4 / 256, 256>>>(W1, wh, wl, nw4);

    bc_kernel<<<T_TOKENS / 64, 256>>>(x, W2, b2, W3, b3);

    cudaFuncSetAttribute(mma_kernel, cudaFuncAttributeMaxDynamicSharedMemorySize,
                         SMEM_TOTAL);
    mma_kernel<<<dim3(DMODEL / 128, T_TOKENS / 128), 256, SMEM_TOTAL>>>(x, b1, y);
}

// round 8
// speedup vs baseline: 2.0613x; 1.0400x over previous
#include <cuda_runtime.h>
#include <cuda_bf16.h>
#include <cstdint>

// y = x * softplus(x@W1^T + b1) * sum_n((x@W2^T+b2)*(x@W3^T+b3))
// B=4, L=2048 -> T=8192 tokens, D=1024, N=16. A input is dead math.
//
// mma.sync.m16n8k16.bf16 (HMMA) + ldmatrix + 3-stage cp.async pipeline.
// 3-pass split precision: x=xh+xl, W1=wh+wl (bf16):
//   z = xh@wh^T + xl@wh^T + xh@wl^T   (xl@wl dropped, ~2^-18 rel)
// R7: 512 threads / 64x16 warp tiles / single-sync multistage / fused x-split.

#define T_TOKENS 8192
#define DMODEL   1024
#define NSTATE   16

__device__ float          g_bc[T_TOKENS];
__device__ __nv_bfloat16  g_xh[T_TOKENS * DMODEL];
__device__ __nv_bfloat16  g_xl[T_TOKENS * DMODEL];
__device__ __nv_bfloat16  g_wh[DMODEL * DMODEL];
__device__ __nv_bfloat16  g_wl[DMODEL * DMODEL];

// ---------------------------------------------------------------------------
__device__ __forceinline__ uint32_t smem_u32(const void* p) {
    uint32_t a;
    asm("{ .reg .u64 t; cvta.to.shared.u64 t, %1; cvt.u32.u64 %0, t; }"
        : "=r"(a) : "l"(p));
    return a;
}

#define SW128(o) ((o) ^ (((o) >> 3) & 0x70))

#define CP_ASYNC16(dst, src) \
    asm volatile("cp.async.cg.shared.global [%0], [%1], 16;" \
                 :: "r"(dst), "l"(src) : "memory")
#define CP_COMMIT() asm volatile("cp.async.commit_group;" ::: "memory")
#define CP_WAIT1()  asm volatile("cp.async.wait_group 1;" ::: "memory")
#define CP_WAIT0()  asm volatile("cp.async.wait_group 0;" ::: "memory")

#define LDSM4(r, addr) \
    asm volatile("ldmatrix.sync.aligned.m8n8.x4.shared.b16 {%0,%1,%2,%3}, [%4];" \
        : "=r"((r)[0]), "=r"((r)[1]), "=r"((r)[2]), "=r"((r)[3]) : "r"(addr))

#define MMA16816(d, a, b0v, b1v) \
    asm volatile("mma.sync.aligned.m16n8k16.row.col.f32.bf16.bf16.f32 " \
        "{%0,%1,%2,%3}, {%4,%5,%6,%7}, {%8,%9}, {%0,%1,%2,%3};" \
        : "+f"((d)[0]), "+f"((d)[1]), "+f"((d)[2]), "+f"((d)[3]) \
        : "r"((a)[0]), "r"((a)[1]), "r"((a)[2]), "r"((a)[3]), \
          "r"(b0v), "r"(b1v))

__device__ __forceinline__ float softplus_f(float z) {
    return fmaxf(z, 0.f) + __logf(1.f + __expf(-fabsf(z)));
}

// ---------------------------------------------------------------------------
// Kernel A: fp32 -> (bf16 hi, bf16 lo) split (used for W1 only; x-split is
// fused into bc_kernel).
// ---------------------------------------------------------------------------
__global__ __launch_bounds__(256) void split_kernel(
    const float* __restrict__ src, __nv_bfloat16* __restrict__ hi,
    __nv_bfloat16* __restrict__ lo, int n4)
{
    int i = blockIdx.x * blockDim.x + threadIdx.x;
    if (i >= n4) return;
    float4 v = reinterpret_cast<const float4*>(src)[i];
    float f[4] = {v.x, v.y, v.z, v.w};
    __nv_bfloat16 h[4], l[4];
    #pragma unroll
    for (int j = 0; j < 4; j++) {
        h[j] = __float2bfloat16(f[j]);
        l[j] = __float2bfloat16(f[j] - __bfloat162float(h[j]));
    }
    ushort4 ho, lov;
    ho.x = *(unsigned short*)&h[0]; ho.y = *(unsigned short*)&h[1];
    ho.z = *(unsigned short*)&h[2]; ho.w = *(unsigned short*)&h[3];
    lov.x = *(unsigned short*)&l[0]; lov.y = *(unsigned short*)&l[1];
    lov.z = *(unsigned short*)&l[2]; lov.w = *(unsigned short*)&l[3];
    reinterpret_cast<ushort4*>(hi)[i] = ho;
    reinterpret_cast<ushort4*>(lo)[i] = lov;
}

// ---------------------------------------------------------------------------
// Kernel B: bc[t] = sum_n (x[t]·W2[n]+b2[n])*(x[t]·W3[n]+b3[n]); also emits
// the bf16 hi/lo split of x (x is already staged here — saves a read pass).
// ---------------------------------------------------------------------------
__global__ __launch_bounds__(256) void bc_split_kernel(
    const float* __restrict__ x,
    const float* __restrict__ W2, const float* __restrict__ b2,
    const float* __restrict__ W3, const float* __restrict__ b3)
{
    const int TPB = 64, KC = 32;
    __shared__ float xs[TPB][36];
    __shared__ float w2s[NSTATE][36];
    __shared__ float w3s[NSTATE][36];
    __shared__ float red[TPB][17];

    int tid = threadIdx.x;
    int n   = tid & 15;
    int gid = tid >> 4;
    int rowBase = blockIdx.x * TPB;

    float accB[4] = {0.f, 0.f, 0.f, 0.f};
    float accC[4] = {0.f, 0.f, 0.f, 0.f};

    for (int k0 = 0; k0 < DMODEL; k0 += KC) {
        #pragma unroll
        for (int j = 0; j < 2; j++) {
            int f = tid * 2 + j, row = f >> 3, q = f & 7;
            size_t gofs = (size_t)(rowBase + row) * DMODEL + k0 + q * 4;
            float4 v = *reinterpret_cast<const float4*>(x + gofs);
            xs[row][q*4+0] = v.x; xs[row][q*4+1] = v.y;
            xs[row][q*4+2] = v.z; xs[row][q*4+3] = v.w;
            // fused split: write bf16 hi/lo of these 4 floats
            float f4[4] = {v.x, v.y, v.z, v.w};
            __nv_bfloat16 h[4], l[4];
            #pragma unroll
            for (int e = 0; e < 4; e++) {
                h[e] = __float2bfloat16(f4[e]);
                l[e] = __float2bfloat16(f4[e] - __bfloat162float(h[e]));
            }
            ushort4 ho, lov;
            ho.x = *(unsigned short*)&h[0]; ho.y = *(unsigned short*)&h[1];
            ho.z = *(unsigned short*)&h[2]; ho.w = *(unsigned short*)&h[3];
            lov.x = *(unsigned short*)&l[0]; lov.y = *(unsigned short*)&l[1];
            lov.z = *(unsigned short*)&l[2]; lov.w = *(unsigned short*)&l[3];
            *reinterpret_cast<ushort4*>(g_xh + gofs) = ho;
            *reinterpret_cast<ushort4*>(g_xl + gofs) = lov;
        }
        {
            int f = tid & 127, row = f >> 3, q = f & 7;
            const float* src = (tid < 128) ? W2 : W3;
            float4 v = *reinterpret_cast<const float4*>(
                src + (size_t)row * DMODEL + k0 + q * 4);
            float (*dst)[36] = (tid < 128) ? w2s : w3s;
            dst[row][q*4+0] = v.x; dst[row][q*4+1] = v.y;
            dst[row][q*4+2] = v.z; dst[row][q*4+3] = v.w;
        }
        __syncthreads();

        #pragma unroll 8
        for (int kk = 0; kk < KC; kk++) {
            float w2 = w2s[n][kk], w3 = w3s[n][kk];
            #pragma unroll
            for (int t = 0; t < 4; t++) {
                float xv = xs[gid*4 + t][kk];
                accB[t] = fmaf(xv, w2, accB[t]);
                accC[t] = fmaf(xv, w3, accC[t]);
            }
        }
        __syncthreads();
    }

    float bb = b2[n], bb3 = b3[n];
    #pragma unroll
    for (int t = 0; t < 4; t++)
        red[gid*4 + t][n] = (accB[t] + bb) * (accC[t] + bb3);
    __syncthreads();

    if (tid < TPB) {
        float s = 0.f;
        #pragma unroll
        for (int nn = 0; nn < NSTATE; nn++) s += red[tid][nn];
        g_bc[rowBase + tid] = s;
    }
}

// ---------------------------------------------------------------------------
// Kernel C: mma.sync bf16 GEMM + fused epilogue.
// CTA 128(M) x 128(N), 512 threads = 16 warps, warp tile 64x16.
// K chunks of 64 bf16 (128B SW128 rows), 48 chunks (3 passes x 16).
// 3-stage cp.async pipeline, single __syncthreads per chunk.
// ---------------------------------------------------------------------------
#define NCHUNKS 48
#define NSTAGES 3
#define TILE_B  16384                       // 128 rows x 128B
#define SMEM_TOTAL (NSTAGES * 2 * TILE_B)   // 96 KB

__global__ __launch_bounds__(512) void mma_kernel(
    const float* __restrict__ x,
    const float* __restrict__ b1,
    float* __restrict__ y)
{
    extern __shared__ char smem[];
    const uint32_t sbase = smem_u32(smem);
    const int tid  = threadIdx.x;
    const int wid  = tid >> 5;
    const int lane = tid & 31;

    const int rowBase = blockIdx.y * 128;
    const int colBase = blockIdx.x * 128;

    const int wm = wid & 1;           // M half (64 rows)
    const int wn = wid >> 1;          // N sixteenth? -> 8 groups of 16 cols

    const __nv_bfloat16* Ap[3] = {
        g_xh + (size_t)rowBase * DMODEL,
        g_xl + (size_t)rowBase * DMODEL,
        g_xh + (size_t)rowBase * DMODEL };
    const __nv_bfloat16* Bp[3] = {
        g_wh + (size_t)colBase * DMODEL,
        g_wh + (size_t)colBase * DMODEL,
        g_wl + (size_t)colBase * DMODEL };

    // ldmatrix per-lane coords (same fragment algebra as validated R6 kernel)
    const int a_row  = (lane & 7) + ((lane >> 3) & 1) * 8;       // 0..15
    const int a_byte = (lane >> 4) * 16;                          // k-half
    const int axor   = (a_row & 7) << 4;
    const int b_row  = ((lane >> 4) & 1) * 8 + (lane & 7);        // n within 16
    const int b_byte = ((lane >> 3) & 1) * 16;                    // k-half
    const int bxor   = (b_row & 7) << 4;

    float acc[4][2][4];
    #pragma unroll
    for (int mi = 0; mi < 4; mi++)
        #pragma unroll
        for (int ni = 0; ni < 2; ni++)
            #pragma unroll
            for (int r = 0; r < 4; r++) acc[mi][ni][r] = 0.f;

    // cp.async coords: f = tid + u*512 in [0,1024): row = f>>3, q = f&7
    const int cp_row0 = tid >> 3;
    const int cp_q    = tid & 7;
    const uint32_t cp_off0 = SW128(cp_row0 * 128 + cp_q * 16);
    const uint32_t cp_off1 = SW128((cp_row0 + 64) * 128 + cp_q * 16);

    // prologue: issue chunks 0 and 1
    #pragma unroll
    for (int gg = 0; gg < 2; gg++) {
        const __nv_bfloat16* pa = Ap[0];
        const __nv_bfloat16* pb = Bp[0];
        int kc = gg << 6;
        uint32_t ab = sbase + (uint32_t)(gg % NSTAGES) * (2 * TILE_B);
        uint32_t bb = ab + TILE_B;
        CP_ASYNC16(ab + cp_off0, pa + (size_t)cp_row0 * DMODEL + kc + cp_q * 8);
        CP_ASYNC16(bb + cp_off0, pb + (size_t)cp_row0 * DMODEL + kc + cp_q * 8);
        CP_ASYNC16(ab + cp_off1, pa + (size_t)(cp_row0 + 64) * DMODEL + kc + cp_q * 8);
        CP_ASYNC16(bb + cp_off1, pb + (size_t)(cp_row0 + 64) * DMODEL + kc + cp_q * 8);
        CP_COMMIT();
    }

    #pragma unroll 1
    for (int g = 0; g < NCHUNKS; g++) {
        if (g < NCHUNKS - 1) { CP_WAIT1(); } else { CP_WAIT0(); }
        __syncthreads();

        // issue chunk g+2 into stage (g+2)%NSTAGES
        if (g + 2 < NCHUNKS) {
            int gg = g + 2;
            const __nv_bfloat16* pa = Ap[gg >> 4];
            const __nv_bfloat16* pb = Bp[gg >> 4];
            int kc = (gg & 15) << 6;
            uint32_t ab = sbase + (uint32_t)(gg % NSTAGES) * (2 * TILE_B);
            uint32_t bb = ab + TILE_B;
            CP_ASYNC16(ab + cp_off0, pa + (size_t)cp_row0 * DMODEL + kc + cp_q * 8);
            CP_ASYNC16(bb + cp_off0, pb + (size_t)cp_row0 * DMODEL + kc + cp_q * 8);
            CP_ASYNC16(ab + cp_off1, pa + (size_t)(cp_row0 + 64) * DMODEL + kc + cp_q * 8);
            CP_ASYNC16(bb + cp_off1, pb + (size_t)(cp_row0 + 64) * DMODEL + kc + cp_q * 8);
            CP_COMMIT();
        }

        const uint32_t aB = sbase + (uint32_t)(g % NSTAGES) * (2 * TILE_B);
        const uint32_t bB = aB + TILE_B;

        #pragma unroll
        for (int s = 0; s < 4; s++) {
            const int kb = s * 32;                 // 16 bf16 = 32B per kstep
            uint32_t afr[4][4];
            #pragma unroll
            for (int mi = 0; mi < 4; mi++) {
                uint32_t addr = aB + (uint32_t)((wm * 64 + mi * 16 + a_row) * 128)
                              + (uint32_t)((kb + a_byte) ^ axor);
                LDSM4(afr[mi], addr);
            }
            uint32_t bfr[4];
            {
                uint32_t addr = bB + (uint32_t)((wn * 16 + b_row) * 128)
                              + (uint32_t)((kb + b_byte) ^ bxor);
                LDSM4(bfr, addr);
            }
            #pragma unroll
            for (int mi = 0; mi < 4; mi++) {
                MMA16816(acc[mi][0], afr[mi], bfr[0], bfr[1]);
                MMA16816(acc[mi][1], afr[mi], bfr[2], bfr[3]);
            }
        }
    }

    // Epilogue: y = x * softplus(z + b1) * bc
    const int gq = lane >> 2;    // row-in-8 group
    const int tq = lane & 3;     // col pair
    #pragma unroll
    for (int mi = 0; mi < 4; mi++) {
        int r0 = rowBase + wm * 64 + mi * 16 + gq;
        int r1 = r0 + 8;
        float bc0 = g_bc[r0], bc1 = g_bc[r1];
        const float* x0 = x + (size_t)r0 * DMODEL;
        const float* x1 = x + (size_t)r1 * DMODEL;
        float* y0 = y + (size_t)r0 * DMODEL;
        float* y1 = y + (size_t)r1 * DMODEL;
        #pragma unroll
        for (int ni = 0; ni < 2; ni++) {
            int c = colBase + wn * 16 + ni * 8 + tq * 2;
            float2 bv  = *reinterpret_cast<const float2*>(b1 + c);
            float2 xv0 = *reinterpret_cast<const float2*>(x0 + c);
            float2 xv1 = *reinterpret_cast<const float2*>(x1 + c);
            float2 o0, o1;
            o0.x = xv0.x * softplus_f(acc[mi][ni][0] + bv.x) * bc0;
            o0.y = xv0.y * softplus_f(acc[mi][ni][1] + bv.y) * bc0;
            o1.x = xv1.x * softplus_f(acc[mi][ni][2] + bv.x) * bc1;
            o1.y = xv1.y * softplus_f(acc[mi][ni][3] + bv.y) * bc1;
            *reinterpret_cast<float2*>(y0 + c) = o0;
            *reinterpret_cast<float2*>(y1 + c) = o1;
        }
    }
}

// ---------------------------------------------------------------------------
extern "C" void kernel_launch(void* const* d_in, const int* in_sizes, int n_in,
                              void* d_out, int out_size)
{
    const float* x  = (const float*)d_in[0];
    const float* W1 = (const float*)d_in[1];
    const float* b1 = (const float*)d_in[2];
    const float* W2 = (const float*)d_in[3];
    const float* b2 = (const float*)d_in[4];
    const float* W3 = (const float*)d_in[5];
    const float* b3 = (const float*)d_in[6];
    float* y = (float*)d_out;

    __nv_bfloat16 *wh, *wl;
    cudaGetSymbolAddress((void**)&wh, g_wh);
    cudaGetSymbolAddress((void**)&wl, g_wl);

    int nw4 = DMODEL * DMODEL / 4;
    split_kernel<<<nw4 / 256, 256>>>(W1, wh, wl, nw4);
    bc_split_kernel<<<T_TOKENS / 64, 256>>>(x, W2, b2, W3, b3);

    cudaFuncSetAttribute(mma_kernel, cudaFuncAttributeMaxDynamicSharedMemorySize,
                         SMEM_TOTAL);
    mma_kernel<<<dim3(DMODEL / 128, T_TOKENS / 128), 512, SMEM_TOTAL>>>(x, b1, y);
}

// round 9
// speedup vs baseline: 2.3184x; 1.1247x over previous
#include <cuda_runtime.h>
#include <cuda_bf16.h>
#include <cstdint>

// y = x * softplus(x@W1^T + b1) * sum_n((x@W2^T+b2)*(x@W3^T+b3))
// B=4, L=2048 -> T=8192 tokens, D=1024, N=16. A input is dead math.
//
// mma.sync.m16n8k16.bf16 (HMMA) + ldmatrix + 3-stage cp.async pipeline.
// 3-pass split precision: x=xh+xl, W1=wh+wl (bf16):
//   z = xh@wh^T + xl@wh^T + xh@wl^T   (xl@wl dropped, ~2^-18 rel)
// R8: 256 threads, 64x32 warp tiles (best LDSM:MMA ratio), register
// fragment double-buffering to hide LDSM latency behind the MMA burst.

#define T_TOKENS 8192
#define DMODEL   1024
#define NSTATE   16

__device__ float          g_bc[T_TOKENS];
__device__ __nv_bfloat16  g_xh[T_TOKENS * DMODEL];
__device__ __nv_bfloat16  g_xl[T_TOKENS * DMODEL];
__device__ __nv_bfloat16  g_wh[DMODEL * DMODEL];
__device__ __nv_bfloat16  g_wl[DMODEL * DMODEL];

// ---------------------------------------------------------------------------
__device__ __forceinline__ uint32_t smem_u32(const void* p) {
    uint32_t a;
    asm("{ .reg .u64 t; cvta.to.shared.u64 t, %1; cvt.u32.u64 %0, t; }"
        : "=r"(a) : "l"(p));
    return a;
}

#define SW128(o) ((o) ^ (((o) >> 3) & 0x70))

#define CP_ASYNC16(dst, src) \
    asm volatile("cp.async.cg.shared.global [%0], [%1], 16;" \
                 :: "r"(dst), "l"(src) : "memory")
#define CP_COMMIT() asm volatile("cp.async.commit_group;" ::: "memory")
#define CP_WAIT1()  asm volatile("cp.async.wait_group 1;" ::: "memory")
#define CP_WAIT0()  asm volatile("cp.async.wait_group 0;" ::: "memory")

#define LDSM4(r, addr) \
    asm volatile("ldmatrix.sync.aligned.m8n8.x4.shared.b16 {%0,%1,%2,%3}, [%4];" \
        : "=r"((r)[0]), "=r"((r)[1]), "=r"((r)[2]), "=r"((r)[3]) : "r"(addr))

#define MMA16816(d, a, b0v, b1v) \
    asm volatile("mma.sync.aligned.m16n8k16.row.col.f32.bf16.bf16.f32 " \
        "{%0,%1,%2,%3}, {%4,%5,%6,%7}, {%8,%9}, {%0,%1,%2,%3};" \
        : "+f"((d)[0]), "+f"((d)[1]), "+f"((d)[2]), "+f"((d)[3]) \
        : "r"((a)[0]), "r"((a)[1]), "r"((a)[2]), "r"((a)[3]), \
          "r"(b0v), "r"(b1v))

__device__ __forceinline__ float softplus_f(float z) {
    return fmaxf(z, 0.f) + __logf(1.f + __expf(-fabsf(z)));
}

// ---------------------------------------------------------------------------
// Kernel A: fp32 -> (bf16 hi, bf16 lo) split (W1 only; x-split fused in B).
// ---------------------------------------------------------------------------
__global__ __launch_bounds__(256) void split_kernel(
    const float* __restrict__ src, __nv_bfloat16* __restrict__ hi,
    __nv_bfloat16* __restrict__ lo, int n4)
{
    int i = blockIdx.x * blockDim.x + threadIdx.x;
    if (i >= n4) return;
    float4 v = reinterpret_cast<const float4*>(src)[i];
    float f[4] = {v.x, v.y, v.z, v.w};
    __nv_bfloat16 h[4], l[4];
    #pragma unroll
    for (int j = 0; j < 4; j++) {
        h[j] = __float2bfloat16(f[j]);
        l[j] = __float2bfloat16(f[j] - __bfloat162float(h[j]));
    }
    ushort4 ho, lov;
    ho.x = *(unsigned short*)&h[0]; ho.y = *(unsigned short*)&h[1];
    ho.z = *(unsigned short*)&h[2]; ho.w = *(unsigned short*)&h[3];
    lov.x = *(unsigned short*)&l[0]; lov.y = *(unsigned short*)&l[1];
    lov.z = *(unsigned short*)&l[2]; lov.w = *(unsigned short*)&l[3];
    reinterpret_cast<ushort4*>(hi)[i] = ho;
    reinterpret_cast<ushort4*>(lo)[i] = lov;
}

// ---------------------------------------------------------------------------
// Kernel B: bc[t] = sum_n (x[t]·W2[n]+b2[n])*(x[t]·W3[n]+b3[n]); also emits
// the bf16 hi/lo split of x (fused — x already staged here).
// ---------------------------------------------------------------------------
__global__ __launch_bounds__(256) void bc_split_kernel(
    const float* __restrict__ x,
    const float* __restrict__ W2, const float* __restrict__ b2,
    const float* __restrict__ W3, const float* __restrict__ b3)
{
    const int TPB = 64, KC = 32;
    __shared__ float xs[TPB][36];
    __shared__ float w2s[NSTATE][36];
    __shared__ float w3s[NSTATE][36];
    __shared__ float red[TPB][17];

    int tid = threadIdx.x;
    int n   = tid & 15;
    int gid = tid >> 4;
    int rowBase = blockIdx.x * TPB;

    float accB[4] = {0.f, 0.f, 0.f, 0.f};
    float accC[4] = {0.f, 0.f, 0.f, 0.f};

    for (int k0 = 0; k0 < DMODEL; k0 += KC) {
        #pragma unroll
        for (int j = 0; j < 2; j++) {
            int f = tid * 2 + j, row = f >> 3, q = f & 7;
            size_t gofs = (size_t)(rowBase + row) * DMODEL + k0 + q * 4;
            float4 v = *reinterpret_cast<const float4*>(x + gofs);
            xs[row][q*4+0] = v.x; xs[row][q*4+1] = v.y;
            xs[row][q*4+2] = v.z; xs[row][q*4+3] = v.w;
            float f4[4] = {v.x, v.y, v.z, v.w};
            __nv_bfloat16 h[4], l[4];
            #pragma unroll
            for (int e = 0; e < 4; e++) {
                h[e] = __float2bfloat16(f4[e]);
                l[e] = __float2bfloat16(f4[e] - __bfloat162float(h[e]));
            }
            ushort4 ho, lov;
            ho.x = *(unsigned short*)&h[0]; ho.y = *(unsigned short*)&h[1];
            ho.z = *(unsigned short*)&h[2]; ho.w = *(unsigned short*)&h[3];
            lov.x = *(unsigned short*)&l[0]; lov.y = *(unsigned short*)&l[1];
            lov.z = *(unsigned short*)&l[2]; lov.w = *(unsigned short*)&l[3];
            *reinterpret_cast<ushort4*>(g_xh + gofs) = ho;
            *reinterpret_cast<ushort4*>(g_xl + gofs) = lov;
        }
        {
            int f = tid & 127, row = f >> 3, q = f & 7;
            const float* src = (tid < 128) ? W2 : W3;
            float4 v = *reinterpret_cast<const float4*>(
                src + (size_t)row * DMODEL + k0 + q * 4);
            float (*dst)[36] = (tid < 128) ? w2s : w3s;
            dst[row][q*4+0] = v.x; dst[row][q*4+1] = v.y;
            dst[row][q*4+2] = v.z; dst[row][q*4+3] = v.w;
        }
        __syncthreads();

        #pragma unroll 8
        for (int kk = 0; kk < KC; kk++) {
            float w2 = w2s[n][kk], w3 = w3s[n][kk];
            #pragma unroll
            for (int t = 0; t < 4; t++) {
                float xv = xs[gid*4 + t][kk];
                accB[t] = fmaf(xv, w2, accB[t]);
                accC[t] = fmaf(xv, w3, accC[t]);
            }
        }
        __syncthreads();
    }

    float bb = b2[n], bb3 = b3[n];
    #pragma unroll
    for (int t = 0; t < 4; t++)
        red[gid*4 + t][n] = (accB[t] + bb) * (accC[t] + bb3);
    __syncthreads();

    if (tid < TPB) {
        float s = 0.f;
        #pragma unroll
        for (int nn = 0; nn < NSTATE; nn++) s += red[tid][nn];
        g_bc[rowBase + tid] = s;
    }
}

// ---------------------------------------------------------------------------
// Kernel C: mma.sync bf16 GEMM + fused epilogue.
// CTA 128x128, 256 threads = 8 warps, warp tile 64x32.
// K chunks of 64 bf16, 48 chunks (3 passes x 16), 3-stage cp.async pipeline,
// register fragment double-buffering across the 4 ksteps of each chunk.
// ---------------------------------------------------------------------------
#define NCHUNKS 48
#define NSTAGES 3
#define TILE_B  16384                       // 128 rows x 128B
#define SMEM_TOTAL (NSTAGES * 2 * TILE_B)   // 96 KB

__global__ __launch_bounds__(256) void mma_kernel(
    const float* __restrict__ x,
    const float* __restrict__ b1,
    float* __restrict__ y)
{
    extern __shared__ char smem[];
    const uint32_t sbase = smem_u32(smem);
    const int tid  = threadIdx.x;
    const int wid  = tid >> 5;
    const int lane = tid & 31;

    const int rowBase = blockIdx.y * 128;
    const int colBase = blockIdx.x * 128;

    const int wm = wid & 1;           // M half (64 rows)
    const int wn = wid >> 1;          // N quarter (32 cols)

    const __nv_bfloat16* Ap[3] = {
        g_xh + (size_t)rowBase * DMODEL,
        g_xl + (size_t)rowBase * DMODEL,
        g_xh + (size_t)rowBase * DMODEL };
    const __nv_bfloat16* Bp[3] = {
        g_wh + (size_t)colBase * DMODEL,
        g_wh + (size_t)colBase * DMODEL,
        g_wl + (size_t)colBase * DMODEL };

    // ldmatrix per-lane coords (validated fragment algebra)
    const int a_row  = (lane & 7) + ((lane >> 3) & 1) * 8;       // 0..15
    const int a_byte = (lane >> 4) * 16;                          // k-half
    const int axor   = (a_row & 7) << 4;
    const int b_row  = ((lane >> 4) & 1) * 8 + (lane & 7);        // n within 16
    const int b_byte = ((lane >> 3) & 1) * 16;                    // k-half
    const int bxor   = (b_row & 7) << 4;

    float acc[4][4][4];
    #pragma unroll
    for (int mi = 0; mi < 4; mi++)
        #pragma unroll
        for (int ni = 0; ni < 4; ni++)
            #pragma unroll
            for (int r = 0; r < 4; r++) acc[mi][ni][r] = 0.f;

    // cp.async coords: f = tid + u*256 in [0,1024): row = f>>3, q = f&7
    const int cp_row = tid >> 3;
    const int cp_q   = tid & 7;
    uint32_t cp_off[4];
    #pragma unroll
    for (int u = 0; u < 4; u++)
        cp_off[u] = SW128((cp_row + u * 32) * 128 + cp_q * 16);

    // prologue: issue chunks 0 and 1
    #pragma unroll
    for (int gg = 0; gg < 2; gg++) {
        const __nv_bfloat16* pa = Ap[0];
        const __nv_bfloat16* pb = Bp[0];
        int kc = gg << 6;
        uint32_t ab = sbase + (uint32_t)gg * (2 * TILE_B);
        uint32_t bb = ab + TILE_B;
        #pragma unroll
        for (int u = 0; u < 4; u++) {
            size_t go = (size_t)(cp_row + u * 32) * DMODEL + kc + cp_q * 8;
            CP_ASYNC16(ab + cp_off[u], pa + go);
            CP_ASYNC16(bb + cp_off[u], pb + go);
        }
        CP_COMMIT();
    }

    // fragment double buffers
    uint32_t afr[2][4][4];
    uint32_t bfr[2][2][4];

    #pragma unroll 1
    for (int g = 0; g < NCHUNKS; g++) {
        if (g < NCHUNKS - 1) { CP_WAIT1(); } else { CP_WAIT0(); }
        __syncthreads();

        // issue chunk g+2 into stage (g+2)%NSTAGES
        if (g + 2 < NCHUNKS) {
            int gg = g + 2;
            const __nv_bfloat16* pa = Ap[gg >> 4];
            const __nv_bfloat16* pb = Bp[gg >> 4];
            int kc = (gg & 15) << 6;
            uint32_t ab = sbase + (uint32_t)(gg % NSTAGES) * (2 * TILE_B);
            uint32_t bb = ab + TILE_B;
            #pragma unroll
            for (int u = 0; u < 4; u++) {
                size_t go = (size_t)(cp_row + u * 32) * DMODEL + kc + cp_q * 8;
                CP_ASYNC16(ab + cp_off[u], pa + go);
                CP_ASYNC16(bb + cp_off[u], pb + go);
            }
            CP_COMMIT();
        }

        const uint32_t aB = sbase + (uint32_t)(g % NSTAGES) * (2 * TILE_B);
        const uint32_t bB = aB + TILE_B;

        // load fragments for kstep 0
        #pragma unroll
        for (int mi = 0; mi < 4; mi++) {
            uint32_t addr = aB + (uint32_t)((wm * 64 + mi * 16 + a_row) * 128)
                          + (uint32_t)(a_byte ^ axor);
            LDSM4(afr[0][mi], addr);
        }
        #pragma unroll
        for (int bt = 0; bt < 2; bt++) {
            uint32_t addr = bB + (uint32_t)((wn * 32 + bt * 16 + b_row) * 128)
                          + (uint32_t)(b_byte ^ bxor);
            LDSM4(bfr[0][bt], addr);
        }

        #pragma unroll
        for (int s = 0; s < 4; s++) {
            const int p = s & 1;
            // prefetch fragments for kstep s+1 while MMAs below execute
            if (s < 3) {
                const int kb = (s + 1) * 32;
                #pragma unroll
                for (int mi = 0; mi < 4; mi++) {
                    uint32_t addr = aB + (uint32_t)((wm * 64 + mi * 16 + a_row) * 128)
                                  + (uint32_t)((kb + a_byte) ^ axor);
                    LDSM4(afr[p ^ 1][mi], addr);
                }
                #pragma unroll
                for (int bt = 0; bt < 2; bt++) {
                    uint32_t addr = bB + (uint32_t)((wn * 32 + bt * 16 + b_row) * 128)
                                  + (uint32_t)((kb + b_byte) ^ bxor);
                    LDSM4(bfr[p ^ 1][bt], addr);
                }
            }
            #pragma unroll
            for (int mi = 0; mi < 4; mi++) {
                #pragma unroll
                for (int ni = 0; ni < 4; ni++) {
                    const uint32_t* bq = bfr[p][ni >> 1];
                    int o = (ni & 1) * 2;
                    MMA16816(acc[mi][ni], afr[p][mi], bq[o], bq[o + 1]);
                }
            }
        }
    }

    // Epilogue: y = x * softplus(z + b1) * bc
    const int gq = lane >> 2;    // row-in-8 group
    const int tq = lane & 3;     // col pair
    #pragma unroll
    for (int mi = 0; mi < 4; mi++) {
        int r0 = rowBase + wm * 64 + mi * 16 + gq;
        int r1 = r0 + 8;
        float bc0 = g_bc[r0], bc1 = g_bc[r1];
        const float* x0 = x + (size_t)r0 * DMODEL;
        const float* x1 = x + (size_t)r1 * DMODEL;
        float* y0 = y + (size_t)r0 * DMODEL;
        float* y1 = y + (size_t)r1 * DMODEL;
        #pragma unroll
        for (int ni = 0; ni < 4; ni++) {
            int c = colBase + wn * 32 + ni * 8 + tq * 2;
            float2 bv  = *reinterpret_cast<const float2*>(b1 + c);
            float2 xv0 = *reinterpret_cast<const float2*>(x0 + c);
            float2 xv1 = *reinterpret_cast<const float2*>(x1 + c);
            float2 o0, o1;
            o0.x = xv0.x * softplus_f(acc[mi][ni][0] + bv.x) * bc0;
            o0.y = xv0.y * softplus_f(acc[mi][ni][1] + bv.y) * bc0;
            o1.x = xv1.x * softplus_f(acc[mi][ni][2] + bv.x) * bc1;
            o1.y = xv1.y * softplus_f(acc[mi][ni][3] + bv.y) * bc1;
            *reinterpret_cast<float2*>(y0 + c) = o0;
            *reinterpret_cast<float2*>(y1 + c) = o1;
        }
    }
}

// ---------------------------------------------------------------------------
extern "C" void kernel_launch(void* const* d_in, const int* in_sizes, int n_in,
                              void* d_out, int out_size)
{
    const float* x  = (const float*)d_in[0];
    const float* W1 = (const float*)d_in[1];
    const float* b1 = (const float*)d_in[2];
    const float* W2 = (const float*)d_in[3];
    const float* b2 = (const float*)d_in[4];
    const float* W3 = (const float*)d_in[5];
    const float* b3 = (const float*)d_in[6];
    float* y = (float*)d_out;

    __nv_bfloat16 *wh, *wl;
    cudaGetSymbolAddress((void**)&wh, g_wh);
    cudaGetSymbolAddress((void**)&wl, g_wl);

    int nw4 = DMODEL * DMODEL / 4;
    split_kernel<<<nw4 / 256, 256>>>(W1, wh, wl, nw4);
    bc_split_kernel<<<T_TOKENS / 64, 256>>>(x, W2, b2, W3, b3);

    cudaFuncSetAttribute(mma_kernel, cudaFuncAttributeMaxDynamicSharedMemorySize,
                         SMEM_TOTAL);
    mma_kernel<<<dim3(DMODEL / 128, T_TOKENS / 128), 256, SMEM_TOTAL>>>(x, b1, y);
}

// round 11
// speedup vs baseline: 2.5183x; 1.0863x over previous
#include <cuda_runtime.h>
#include <cuda_bf16.h>
#include <cstdint>

// y = x * softplus(x@W1^T + b1) * sum_n((x@W2^T+b2)*(x@W3^T+b3))
// B=4, L=2048 -> T=8192 tokens, D=1024, N=16. A input is dead math.
//
// mma.sync.m16n8k16.bf16 (HMMA) + ldmatrix + 3-stage cp.async pipeline.
// 3-pass split precision: x=xh+xl, W1=wh+wl (bf16):
//   z = xh@wh^T + xl@wh^T + xh@wl^T   (xl@wl dropped, ~2^-18 rel)
// R9: CTA 128x64, 128 threads (4 warps of 64x32), 72KB smem -> 3 CTAs/SM.
// Cross-CTA overlap hides barrier/cp.async stalls that capped tensor% at ~50.

#define T_TOKENS 8192
#define DMODEL   1024
#define NSTATE   16

__device__ float          g_bc[T_TOKENS];
__device__ __nv_bfloat16  g_xh[T_TOKENS * DMODEL];
__device__ __nv_bfloat16  g_xl[T_TOKENS * DMODEL];
__device__ __nv_bfloat16  g_wh[DMODEL * DMODEL];
__device__ __nv_bfloat16  g_wl[DMODEL * DMODEL];

// ---------------------------------------------------------------------------
__device__ __forceinline__ uint32_t smem_u32(const void* p) {
    uint32_t a;
    asm("{ .reg .u64 t; cvta.to.shared.u64 t, %1; cvt.u32.u64 %0, t; }"
        : "=r"(a) : "l"(p));
    return a;
}

#define SW128(o) ((o) ^ (((o) >> 3) & 0x70))

#define CP_ASYNC16(dst, src) \
    asm volatile("cp.async.cg.shared.global [%0], [%1], 16;" \
                 :: "r"(dst), "l"(src) : "memory")
#define CP_COMMIT() asm volatile("cp.async.commit_group;" ::: "memory")
#define CP_WAIT1()  asm volatile("cp.async.wait_group 1;" ::: "memory")
#define CP_WAIT0()  asm volatile("cp.async.wait_group 0;" ::: "memory")

#define LDSM4(r, addr) \
    asm volatile("ldmatrix.sync.aligned.m8n8.x4.shared.b16 {%0,%1,%2,%3}, [%4];" \
        : "=r"((r)[0]), "=r"((r)[1]), "=r"((r)[2]), "=r"((r)[3]) : "r"(addr))

#define MMA16816(d, a, b0v, b1v) \
    asm volatile("mma.sync.aligned.m16n8k16.row.col.f32.bf16.bf16.f32 " \
        "{%0,%1,%2,%3}, {%4,%5,%6,%7}, {%8,%9}, {%0,%1,%2,%3};" \
        : "+f"((d)[0]), "+f"((d)[1]), "+f"((d)[2]), "+f"((d)[3]) \
        : "r"((a)[0]), "r"((a)[1]), "r"((a)[2]), "r"((a)[3]), \
          "r"(b0v), "r"(b1v))

__device__ __forceinline__ float softplus_f(float z) {
    return fmaxf(z, 0.f) + __logf(1.f + __expf(-fabsf(z)));
}

// ---------------------------------------------------------------------------
// Kernel A: fp32 -> (bf16 hi, bf16 lo) split (W1 only; x-split fused in B).
// ---------------------------------------------------------------------------
__global__ __launch_bounds__(256) void split_kernel(
    const float* __restrict__ src, __nv_bfloat16* __restrict__ hi,
    __nv_bfloat16* __restrict__ lo, int n4)
{
    int i = blockIdx.x * blockDim.x + threadIdx.x;
    if (i >= n4) return;
    float4 v = reinterpret_cast<const float4*>(src)[i];
    float f[4] = {v.x, v.y, v.z, v.w};
    __nv_bfloat16 h[4], l[4];
    #pragma unroll
    for (int j = 0; j < 4; j++) {
        h[j] = __float2bfloat16(f[j]);
        l[j] = __float2bfloat16(f[j] - __bfloat162float(h[j]));
    }
    ushort4 ho, lov;
    ho.x = *(unsigned short*)&h[0]; ho.y = *(unsigned short*)&h[1];
    ho.z = *(unsigned short*)&h[2]; ho.w = *(unsigned short*)&h[3];
    lov.x = *(unsigned short*)&l[0]; lov.y = *(unsigned short*)&l[1];
    lov.z = *(unsigned short*)&l[2]; lov.w = *(unsigned short*)&l[3];
    reinterpret_cast<ushort4*>(hi)[i] = ho;
    reinterpret_cast<ushort4*>(lo)[i] = lov;
}

// ---------------------------------------------------------------------------
// Kernel B: bc[t] = sum_n (x[t]·W2[n]+b2[n])*(x[t]·W3[n]+b3[n]); also emits
// the bf16 hi/lo split of x (fused — x already staged here).
// ---------------------------------------------------------------------------
__global__ __launch_bounds__(256) void bc_split_kernel(
    const float* __restrict__ x,
    const float* __restrict__ W2, const float* __restrict__ b2,
    const float* __restrict__ W3, const float* __restrict__ b3)
{
    const int TPB = 64, KC = 32;
    __shared__ float xs[TPB][36];
    __shared__ float w2s[NSTATE][36];
    __shared__ float w3s[NSTATE][36];
    __shared__ float red[TPB][17];

    int tid = threadIdx.x;
    int n   = tid & 15;
    int gid = tid >> 4;
    int rowBase = blockIdx.x * TPB;

    float accB[4] = {0.f, 0.f, 0.f, 0.f};
    float accC[4] = {0.f, 0.f, 0.f, 0.f};

    for (int k0 = 0; k0 < DMODEL; k0 += KC) {
        #pragma unroll
        for (int j = 0; j < 2; j++) {
            int f = tid * 2 + j, row = f >> 3, q = f & 7;
            size_t gofs = (size_t)(rowBase + row) * DMODEL + k0 + q * 4;
            float4 v = *reinterpret_cast<const float4*>(x + gofs);
            xs[row][q*4+0] = v.x; xs[row][q*4+1] = v.y;
            xs[row][q*4+2] = v.z; xs[row][q*4+3] = v.w;
            float f4[4] = {v.x, v.y, v.z, v.w};
            __nv_bfloat16 h[4], l[4];
            #pragma unroll
            for (int e = 0; e < 4; e++) {
                h[e] = __float2bfloat16(f4[e]);
                l[e] = __float2bfloat16(f4[e] - __bfloat162float(h[e]));
            }
            ushort4 ho, lov;
            ho.x = *(unsigned short*)&h[0]; ho.y = *(unsigned short*)&h[1];
            ho.z = *(unsigned short*)&h[2]; ho.w = *(unsigned short*)&h[3];
            lov.x = *(unsigned short*)&l[0]; lov.y = *(unsigned short*)&l[1];
            lov.z = *(unsigned short*)&l[2]; lov.w = *(unsigned short*)&l[3];
            *reinterpret_cast<ushort4*>(g_xh + gofs) = ho;
            *reinterpret_cast<ushort4*>(g_xl + gofs) = lov;
        }
        {
            int f = tid & 127, row = f >> 3, q = f & 7;
            const float* src = (tid < 128) ? W2 : W3;
            float4 v = *reinterpret_cast<const float4*>(
                src + (size_t)row * DMODEL + k0 + q * 4);
            float (*dst)[36] = (tid < 128) ? w2s : w3s;
            dst[row][q*4+0] = v.x; dst[row][q*4+1] = v.y;
            dst[row][q*4+2] = v.z; dst[row][q*4+3] = v.w;
        }
        __syncthreads();

        #pragma unroll 8
        for (int kk = 0; kk < KC; kk++) {
            float w2 = w2s[n][kk], w3 = w3s[n][kk];
            #pragma unroll
            for (int t = 0; t < 4; t++) {
                float xv = xs[gid*4 + t][kk];
                accB[t] = fmaf(xv, w2, accB[t]);
                accC[t] = fmaf(xv, w3, accC[t]);
            }
        }
        __syncthreads();
    }

    float bb = b2[n], bb3 = b3[n];
    #pragma unroll
    for (int t = 0; t < 4; t++)
        red[gid*4 + t][n] = (accB[t] + bb) * (accC[t] + bb3);
    __syncthreads();

    if (tid < TPB) {
        float s = 0.f;
        #pragma unroll
        for (int nn = 0; nn < NSTATE; nn++) s += red[tid][nn];
        g_bc[rowBase + tid] = s;
    }
}

// ---------------------------------------------------------------------------
// Kernel C: mma.sync bf16 GEMM + fused epilogue.
// CTA 128(M) x 64(N), 128 threads = 4 warps, warp tile 64x32.
// K chunks of 64 bf16, 48 chunks (3 passes x 16), 3-stage cp.async pipeline,
// register fragment double-buffering. 72KB smem -> 3 CTAs/SM resident.
// ---------------------------------------------------------------------------
#define NCHUNKS 48
#define NSTAGES 3
#define A_BYTES 16384                       // 128 rows x 128B
#define B_BYTES 8192                        // 64 rows x 128B
#define STAGE_B (A_BYTES + B_BYTES)         // 24 KB
#define SMEM_TOTAL (NSTAGES * STAGE_B)      // 72 KB

__global__ __launch_bounds__(128) void mma_kernel(
    const float* __restrict__ x,
    const float* __restrict__ b1,
    float* __restrict__ y)
{
    extern __shared__ char smem[];
    const uint32_t sbase = smem_u32(smem);
    const int tid  = threadIdx.x;
    const int wid  = tid >> 5;
    const int lane = tid & 31;

    const int rowBase = blockIdx.y * 128;
    const int colBase = blockIdx.x * 64;

    const int wm = wid & 1;           // M half (64 rows)
    const int wn = wid >> 1;          // N half (32 cols)

    const __nv_bfloat16* Ap[3] = {
        g_xh + (size_t)rowBase * DMODEL,
        g_xl + (size_t)rowBase * DMODEL,
        g_xh + (size_t)rowBase * DMODEL };
    const __nv_bfloat16* Bp[3] = {
        g_wh + (size_t)colBase * DMODEL,
        g_wh + (size_t)colBase * DMODEL,
        g_wl + (size_t)colBase * DMODEL };

    // ldmatrix per-lane coords (validated fragment algebra)
    const int a_row  = (lane & 7) + ((lane >> 3) & 1) * 8;       // 0..15
    const int a_byte = (lane >> 4) * 16;                          // k-half
    const int axor   = (a_row & 7) << 4;
    const int b_row  = ((lane >> 4) & 1) * 8 + (lane & 7);        // n within 16
    const int b_byte = ((lane >> 3) & 1) * 16;                    // k-half
    const int bxor   = (b_row & 7) << 4;

    float acc[4][4][4];
    #pragma unroll
    for (int mi = 0; mi < 4; mi++)
        #pragma unroll
        for (int ni = 0; ni < 4; ni++)
            #pragma unroll
            for (int r = 0; r < 4; r++) acc[mi][ni][r] = 0.f;

    // cp.async coords (128 threads):
    //   A: f = tid + u*128, u<8  -> row = f>>3 (0..127), q = f&7
    //   B: f = tid + u*128, u<4  -> row (0..63)
    const int cp_row = tid >> 3;      // 0..15
    const int cp_q   = tid & 7;

    // prologue: issue chunks 0 and 1
    #pragma unroll
    for (int gg = 0; gg < 2; gg++) {
        const __nv_bfloat16* pa = Ap[0];
        const __nv_bfloat16* pb = Bp[0];
        int kc = gg << 6;
        uint32_t ab = sbase + (uint32_t)gg * STAGE_B;
        uint32_t bb = ab + A_BYTES;
        #pragma unroll
        for (int u = 0; u < 8; u++) {
            int row = cp_row + u * 16;
            CP_ASYNC16(ab + SW128(row * 128 + cp_q * 16),
                       pa + (size_t)row * DMODEL + kc + cp_q * 8);
        }
        #pragma unroll
        for (int u = 0; u < 4; u++) {
            int row = cp_row + u * 16;
            CP_ASYNC16(bb + SW128(row * 128 + cp_q * 16),
                       pb + (size_t)row * DMODEL + kc + cp_q * 8);
        }
        CP_COMMIT();
    }

    // fragment double buffers
    uint32_t afr[2][4][4];
    uint32_t bfr[2][2][4];

    #pragma unroll 1
    for (int g = 0; g < NCHUNKS; g++) {
        if (g < NCHUNKS - 1) { CP_WAIT1(); } else { CP_WAIT0(); }
        __syncthreads();

        // issue chunk g+2 into stage (g+2)%NSTAGES
        if (g + 2 < NCHUNKS) {
            int gg = g + 2;
            const __nv_bfloat16* pa = Ap[gg >> 4];
            const __nv_bfloat16* pb = Bp[gg >> 4];
            int kc = (gg & 15) << 6;
            uint32_t ab = sbase + (uint32_t)(gg % NSTAGES) * STAGE_B;
            uint32_t bb = ab + A_BYTES;
            #pragma unroll
            for (int u = 0; u < 8; u++) {
                int row = cp_row + u * 16;
                CP_ASYNC16(ab + SW128(row * 128 + cp_q * 16),
                           pa + (size_t)row * DMODEL + kc + cp_q * 8);
            }
            #pragma unroll
            for (int u = 0; u < 4; u++) {
                int row = cp_row + u * 16;
                CP_ASYNC16(bb + SW128(row * 128 + cp_q * 16),
                           pb + (size_t)row * DMODEL + kc + cp_q * 8);
            }
            CP_COMMIT();
        }

        const uint32_t aB = sbase + (uint32_t)(g % NSTAGES) * STAGE_B;
        const uint32_t bB = aB + A_BYTES;

        // load fragments for kstep 0
        #pragma unroll
        for (int mi = 0; mi < 4; mi++) {
            uint32_t addr = aB + (uint32_t)((wm * 64 + mi * 16 + a_row) * 128)
                          + (uint32_t)(a_byte ^ axor);
            LDSM4(afr[0][mi], addr);
        }
        #pragma unroll
        for (int bt = 0; bt < 2; bt++) {
            uint32_t addr = bB + (uint32_t)((wn * 32 + bt * 16 + b_row) * 128)
                          + (uint32_t)(b_byte ^ bxor);
            LDSM4(bfr[0][bt], addr);
        }

        #pragma unroll
        for (int s = 0; s < 4; s++) {
            const int p = s & 1;
            if (s < 3) {
                const int kb = (s + 1) * 32;
                #pragma unroll
                for (int mi = 0; mi < 4; mi++) {
                    uint32_t addr = aB + (uint32_t)((wm * 64 + mi * 16 + a_row) * 128)
                                  + (uint32_t)((kb + a_byte) ^ axor);
                    LDSM4(afr[p ^ 1][mi], addr);
                }
                #pragma unroll
                for (int bt = 0; bt < 2; bt++) {
                    uint32_t addr = bB + (uint32_t)((wn * 32 + bt * 16 + b_row) * 128)
                                  + (uint32_t)((kb + b_byte) ^ bxor);
                    LDSM4(bfr[p ^ 1][bt], addr);
                }
            }
            #pragma unroll
            for (int mi = 0; mi < 4; mi++) {
                #pragma unroll
                for (int ni = 0; ni < 4; ni++) {
                    const uint32_t* bq = bfr[p][ni >> 1];
                    int o = (ni & 1) * 2;
                    MMA16816(acc[mi][ni], afr[p][mi], bq[o], bq[o + 1]);
                }
            }
        }
    }

    // Epilogue: y = x * softplus(z + b1) * bc
    const int gq = lane >> 2;    // row-in-8 group
    const int tq = lane & 3;     // col pair
    #pragma unroll
    for (int mi = 0; mi < 4; mi++) {
        int r0 = rowBase + wm * 64 + mi * 16 + gq;
        int r1 = r0 + 8;
        float bc0 = g_bc[r0], bc1 = g_bc[r1];
        const float* x0 = x + (size_t)r0 * DMODEL;
        const float* x1 = x + (size_t)r1 * DMODEL;
        float* y0 = y + (size_t)r0 * DMODEL;
        float* y1 = y + (size_t)r1 * DMODEL;
        #pragma unroll
        for (int ni = 0; ni < 4; ni++) {
            int c = colBase + wn * 32 + ni * 8 + tq * 2;
            float2 bv  = *reinterpret_cast<const float2*>(b1 + c);
            float2 xv0 = *reinterpret_cast<const float2*>(x0 + c);
            float2 xv1 = *reinterpret_cast<const float2*>(x1 + c);
            float2 o0, o1;
            o0.x = xv0.x * softplus_f(acc[mi][ni][0] + bv.x) * bc0;
            o0.y = xv0.y * softplus_f(acc[mi][ni][1] + bv.y) * bc0;
            o1.x = xv1.x * softplus_f(acc[mi][ni][2] + bv.x) * bc1;
            o1.y = xv1.y * softplus_f(acc[mi][ni][3] + bv.y) * bc1;
            *reinterpret_cast<float2*>(y0 + c) = o0;
            *reinterpret_cast<float2*>(y1 + c) = o1;
        }
    }
}

// ---------------------------------------------------------------------------
extern "C" void kernel_launch(void* const* d_in, const int* in_sizes, int n_in,
                              void* d_out, int out_size)
{
    const float* x  = (const float*)d_in[0];
    const float* W1 = (const float*)d_in[1];
    const float* b1 = (const float*)d_in[2];
    const float* W2 = (const float*)d_in[3];
    const float* b2 = (const float*)d_in[4];
    const float* W3 = (const float*)d_in[5];
    const float* b3 = (const float*)d_in[6];
    float* y = (float*)d_out;

    __nv_bfloat16 *wh, *wl;
    cudaGetSymbolAddress((void**)&wh, g_wh);
    cudaGetSymbolAddress((void**)&wl, g_wl);

    int nw4 = DMODEL * DMODEL / 4;
    split_kernel<<<nw4 / 256, 256>>>(W1, wh, wl, nw4);
    bc_split_kernel<<<T_TOKENS / 64, 256>>>(x, W2, b2, W3, b3);

    cudaFuncSetAttribute(mma_kernel, cudaFuncAttributeMaxDynamicSharedMemorySize,
                         SMEM_TOTAL);
    mma_kernel<<<dim3(DMODEL / 64, T_TOKENS / 128), 128, SMEM_TOTAL>>>(x, b1, y);
}